// round 3
// baseline (speedup 1.0000x reference)
#include <cuda_runtime.h>
#include <cuda_bf16.h>

#define BB 8
#define TT 64
#define NN 2048
#define HH 64
#define FF 64
#define GG 192
#define EE 32768

#define WSZ (2048ULL*64*192)   // 25,165,824 elements per big weight

// ---------------- device scratch (static globals; no allocation) ----------------
__device__ unsigned short g_Wih[WSZ];        // bf16 bits, layout [n][k][g]
__device__ unsigned short g_Whh[WSZ];        // bf16 bits, layout [n][k][g]
__device__ float g_Wmix_t[128*64];           // [k][h]
__device__ float g_Wmsg_t[64*64];            // [k][h]
__device__ float g_state[(size_t)BB*NN*HH];  // [b][n][h]
__device__ float g_m[2][(size_t)BB*NN*HH];   // message ping-pong [b][n][h]
__device__ int   g_deg[NN];
__device__ int   g_rowptr[NN+1];
__device__ int   g_csrc[EE];
__device__ float g_losspart[NN];
__device__ int   g_maskcnt;
__device__ int   g_masktype;                 // 0=uint8, 1=int32, 2=float32

__device__ __forceinline__ unsigned short f2bf(float f) {
    __nv_bfloat16 h = __float2bfloat16(f);
    return *reinterpret_cast<unsigned short*>(&h);
}
__device__ __forceinline__ float bf2f(unsigned short u) {
    return __uint_as_float(((unsigned int)u) << 16);
}

__device__ __forceinline__ int mask_at(const void* m, size_t i, int mt) {
    if (mt == 2) return ((const float*)m)[i] != 0.f;
    if (mt == 1) return ((const int*)m)[i]   != 0;
    return ((const unsigned char*)m)[i] != 0;
}

// ---------------- mask dtype autodetect (reads first 16KB, safe for all variants) --
__global__ void k_detect(const unsigned int* __restrict__ mw) {
    __shared__ int sI, sF;
    if (threadIdx.x == 0) { sI = 1; sF = 1; }
    __syncthreads();
    int okI = 1, okF = 1;
    for (int i = threadIdx.x; i < 4096; i += 256) {
        unsigned v = mw[i];
        okI &= (v <= 1u) ? 1 : 0;
        okF &= (v == 0u || v == 0x3F800000u) ? 1 : 0;
    }
    if (!okI) atomicAnd(&sI, 0);
    if (!okF) atomicAnd(&sF, 0);
    __syncthreads();
    if (threadIdx.x == 0) g_masktype = sF ? 2 : (sI ? 1 : 0);
}

// ---------------- prologue: transpose big per-node weights to [n][k][g] bf16 ----
__global__ void k_transpose_w(const float* __restrict__ Wih, const float* __restrict__ Whh) {
    int blk  = blockIdx.x;
    int n    = blk >> 1;
    int koff = (blk & 1) * 32;
    __shared__ float tile[192*33];
    int tid = threadIdx.x; // 256
    for (int pass = 0; pass < 2; ++pass) {
        const float* W = pass ? Whh : Wih;
        unsigned short* O = pass ? g_Whh : g_Wih;
        for (int i = tid; i < 192*32; i += 256) {
            int g = i >> 5, kk = i & 31;
            tile[g*33 + kk] = W[((size_t)n*192 + g)*64 + koff + kk];
        }
        __syncthreads();
        for (int o = tid; o < 32*192; o += 256) {
            int kk = o / 192, g = o % 192;
            O[((size_t)n*64 + koff + kk)*192 + g] = f2bf(tile[g*33 + kk]);
        }
        __syncthreads();
    }
}

__global__ void k_transpose_small(const float* __restrict__ Wmix, const float* __restrict__ Wmsg) {
    int i = blockIdx.x*blockDim.x + threadIdx.x;
    if (i < 128*64) { int k = i / 64, h = i % 64; g_Wmix_t[i] = Wmix[h*128 + k]; }
    if (i < 64*64)  { int k = i / 64, h = i % 64; g_Wmsg_t[i] = Wmsg[h*64 + k]; }
}

// ---------------- CSR build (deterministic) ----------------
__global__ void k_count(const int* __restrict__ ei) {
    const int* dst = ei + EE;
    int w    = (blockIdx.x*blockDim.x + threadIdx.x) >> 5;
    int lane = threadIdx.x & 31;
    if (w >= NN) return;
    int cnt = 0;
    for (int e = lane; e < EE; e += 32) cnt += (dst[e] == w) ? 1 : 0;
    #pragma unroll
    for (int off = 16; off; off >>= 1) cnt += __shfl_down_sync(0xffffffffu, cnt, off);
    if (lane == 0) g_deg[w] = cnt;
}

__global__ void k_scan() {
    __shared__ int s[NN];
    int t = threadIdx.x; // 1024
    s[t] = g_deg[t]; s[t+1024] = g_deg[t+1024];
    __syncthreads();
    for (int off = 1; off < NN; off <<= 1) {
        int v0 = s[t], v1 = s[t+1024];
        int u0 = (t >= off) ? s[t-off] : 0;
        int u1 = ((t+1024) >= off) ? s[t+1024-off] : 0;
        __syncthreads();
        s[t] = v0 + u0; s[t+1024] = v1 + u1;
        __syncthreads();
    }
    g_rowptr[t+1] = s[t];
    g_rowptr[t+1025] = s[t+1024];
    if (t == 0) g_rowptr[0] = 0;
}

__global__ void k_fill(const int* __restrict__ ei) {
    const int* src = ei;
    const int* dst = ei + EE;
    int w    = (blockIdx.x*blockDim.x + threadIdx.x) >> 5;
    int lane = threadIdx.x & 31;
    if (w >= NN) return;
    int off = g_rowptr[w];
    for (int base = 0; base < EE; base += 32) {
        int e = base + lane;
        bool match = (dst[e] == w);
        unsigned bal = __ballot_sync(0xffffffffu, match);
        if (match) {
            int pos = off + __popc(bal & ((1u << lane) - 1u));
            g_csrc[pos] = src[e];
        }
        off += __popc(bal);
    }
}

// ---------------- init ----------------
__global__ void k_init(const float* __restrict__ b_msg) {
    int i = blockIdx.x*256 + threadIdx.x;
    g_state[i] = 0.f;
    g_m[0][i]  = b_msg[i & 63];
    if (i < NN) g_losspart[i] = 0.f;
    if (i == 0) g_maskcnt = 0;
}

__global__ void k_masksum(const void* __restrict__ m) {
    __shared__ int sh[256];
    int mt = g_masktype;
    int tid = threadIdx.x;
    int cnt = 0;
    for (size_t i = (size_t)blockIdx.x*256 + tid; i < (size_t)BB*TT*NN; i += (size_t)gridDim.x*256)
        cnt += mask_at(m, i, mt);
    sh[tid] = cnt; __syncthreads();
    for (int off = 128; off; off >>= 1) { if (tid < off) sh[tid] += sh[tid+off]; __syncthreads(); }
    if (tid == 0) atomicAdd(&g_maskcnt, sh[0]);
}

// ---------------- fused per-timestep kernel ----------------
__global__ __launch_bounds__(384, 2) void k_step(
    const float* __restrict__ x, const float* __restrict__ targets,
    const void* __restrict__ tmask,
    const float* __restrict__ b_msg, const float* __restrict__ b_mix,
    const float* __restrict__ b_ih, const float* __restrict__ b_hh,
    const float* __restrict__ W_read, const float* __restrict__ b_read,
    int t, int parity)
{
    const int n   = blockIdx.x;
    const int tid = threadIdx.x;
    const float* __restrict__ mprev = g_m[parity];
    float* __restrict__ mnext = g_m[parity ^ 1];

    __shared__ __align__(16) float st_s[512];
    __shared__ __align__(16) float x_s[512];
    __shared__ __align__(16) float agg_s[512];
    __shared__ __align__(16) float m2_s[512];
    __shared__ __align__(16) float ns_s[512];
    __shared__ __align__(16) float gi_s[8*GG];
    __shared__ __align__(16) float gh_s[8*GG];

    // ---- P0: load state and x_t ----
    for (int p = tid; p < 512; p += 384) {
        int b = p >> 6, h = p & 63;
        st_s[p] = g_state[((size_t)b*NN + n)*HH + h];
        x_s[p]  = x[(((size_t)b*TT + t)*NN + n)*FF + h];
    }
    // ---- P1: gather incoming messages (deterministic CSR order) ----
    {
        int rs = g_rowptr[n], re = g_rowptr[n+1];
        int p1 = tid + 384;
        int b0 = tid >> 6, h0 = tid & 63;
        int b1 = p1 >> 6, h1 = p1 & 63;
        bool has1 = (p1 < 512);
        float a0 = 0.f, a1 = 0.f;
        for (int e = rs; e < re; ++e) {
            int s = g_csrc[e];
            a0 += mprev[((size_t)b0*NN + s)*HH + h0];
            if (has1) a1 += mprev[((size_t)b1*NN + s)*HH + h1];
        }
        agg_s[tid] = a0;
        if (has1) agg_s[p1] = a1;
    }
    __syncthreads();

    // ---- P2: m2 = W_mix @ [agg, x] + b_mix ----
    for (int p = tid; p < 512; p += 384) {
        int b = p >> 6, h = p & 63;
        float acc = b_mix[h];
        const float* ag = &agg_s[b*64];
        const float* xr = &x_s[b*64];
        #pragma unroll 8
        for (int k = 0; k < 64; ++k) acc += g_Wmix_t[k*64 + h] * ag[k];
        #pragma unroll 8
        for (int k = 0; k < 64; ++k) acc += g_Wmix_t[(64 + k)*64 + h] * xr[k];
        m2_s[p] = acc;
    }
    __syncthreads();

    // ---- P3: gi = W_ih[n]@m2, gh = W_hh[n]@state (bf16 weights streamed) ----
    {
        int half = (tid >= 192) ? 1 : 0;
        int g = tid - half*192;
        const unsigned short* __restrict__ Wp =
            (half ? g_Whh : g_Wih) + ((size_t)n*HH)*GG + g;
        const float* __restrict__ vec  = half ? st_s : m2_s;
        const float* __restrict__ bias = half ? b_hh : b_ih;
        float bv = bias[n*GG + g];
        float acc[8];
        #pragma unroll
        for (int b = 0; b < 8; ++b) acc[b] = bv;
        #pragma unroll 4
        for (int k = 0; k < 64; ++k) {
            float w = bf2f(__ldcs(Wp + (size_t)k*GG));
            #pragma unroll
            for (int b = 0; b < 8; ++b) acc[b] += w * vec[b*64 + k];
        }
        float* o = half ? gh_s : gi_s;
        #pragma unroll
        for (int b = 0; b < 8; ++b) o[b*GG + g] = acc[b];
    }
    __syncthreads();

    // ---- P4: GRU elementwise ----
    for (int p = tid; p < 512; p += 384) {
        int b = p >> 6, h = p & 63;
        float ir = gi_s[b*GG + h],        hr = gh_s[b*GG + h];
        float iz = gi_s[b*GG + 64 + h],   hz = gh_s[b*GG + 64 + h];
        float in_= gi_s[b*GG + 128 + h],  hn = gh_s[b*GG + 128 + h];
        float r  = 1.f / (1.f + __expf(-(ir + hr)));
        float z  = 1.f / (1.f + __expf(-(iz + hz)));
        float nc = tanhf(in_ + r * hn);
        float ns = (1.f - z) * nc + z * st_s[p];
        ns_s[p] = ns;
        g_state[((size_t)b*NN + n)*HH + h] = ns;
    }
    __syncthreads();

    // ---- P5: next-step message m = W_msg @ new_state + b_msg ----
    for (int p = tid; p < 512; p += 384) {
        int b = p >> 6, h = p & 63;
        float acc = b_msg[h];
        const float* nr = &ns_s[b*64];
        #pragma unroll 8
        for (int k = 0; k < 64; ++k) acc += g_Wmsg_t[k*64 + h] * nr[k];
        mnext[((size_t)b*NN + n)*HH + h] = acc;
    }

    // ---- P6: readout + masked loss (per-node accumulator, deterministic) ----
    if (tid < 8) {
        int b = tid;
        float dot = b_read[0];
        #pragma unroll 8
        for (int h = 0; h < 64; ++h) dot += W_read[h] * ns_s[b*64 + h];
        size_t ti = ((size_t)b*TT + t)*NN + n;
        float tv = targets[ti];
        float d  = dot - tv;
        int   mk = mask_at(tmask, ti, g_masktype);
        float l  = mk ? 0.5f * d * d : 0.f;
        #pragma unroll
        for (int off = 4; off; off >>= 1) l += __shfl_down_sync(0xFFu, l, off);
        if (b == 0) g_losspart[n] += l;
    }
}

// ---------------- finalize ----------------
__global__ void k_final(float* __restrict__ out) {
    __shared__ float sh[256];
    int tid = threadIdx.x;
    float s = 0.f;
    for (int i = tid; i < NN; i += 256) s += g_losspart[i];
    sh[tid] = s; __syncthreads();
    for (int off = 128; off; off >>= 1) { if (tid < off) sh[tid] += sh[tid+off]; __syncthreads(); }
    if (tid == 0) out[0] = sh[0] / (float)g_maskcnt;
}

// ---------------- launch ----------------
extern "C" void kernel_launch(void* const* d_in, const int* in_sizes, int n_in,
                              void* d_out, int out_size) {
    const float*         x       = (const float*)d_in[0];
    const float*         targets = (const float*)d_in[1];
    const void*          tmask   = (const void*)d_in[2];
    const int*           ei      = (const int*)d_in[3];
    const float*         W_msg   = (const float*)d_in[4];
    const float*         b_msg   = (const float*)d_in[5];
    const float*         W_mix   = (const float*)d_in[6];
    const float*         b_mix   = (const float*)d_in[7];
    const float*         W_ih    = (const float*)d_in[8];
    const float*         W_hh    = (const float*)d_in[9];
    const float*         b_ih    = (const float*)d_in[10];
    const float*         b_hh    = (const float*)d_in[11];
    const float*         W_read  = (const float*)d_in[12];
    const float*         b_read  = (const float*)d_in[13];

    k_detect<<<1, 256>>>((const unsigned int*)tmask);
    k_transpose_w<<<4096, 256>>>(W_ih, W_hh);
    k_transpose_small<<<32, 256>>>(W_mix, W_msg);
    k_count<<<256, 256>>>(ei);
    k_scan<<<1, 1024>>>();
    k_fill<<<256, 256>>>(ei);
    k_init<<<4096, 256>>>(b_msg);
    k_masksum<<<256, 256>>>(tmask);

    for (int t = 0; t < TT; ++t) {
        k_step<<<NN, 384>>>(x, targets, tmask, b_msg, b_mix, b_ih, b_hh,
                            W_read, b_read, t, t & 1);
    }
    k_final<<<1, 256>>>((float*)d_out);
}

// round 4
// speedup vs baseline: 1.0364x; 1.0364x over previous
#include <cuda_runtime.h>
#include <cuda_bf16.h>

#define BB 8
#define TT 64
#define NN 2048
#define HH 64
#define FF 64
#define GG 192
#define EE 32768

#define WSZ (2048ULL*64*192)

// ---------------- device scratch ----------------
__device__ unsigned short g_Wih[WSZ];        // bf16 bits, [n][k][g]
__device__ unsigned short g_Whh[WSZ];        // bf16 bits, [n][k][g]
__device__ float g_Wmix_t[128*64];           // [k][h]
__device__ float g_Wmsg_t[64*64];            // [k][h]
__device__ float g_state[(size_t)BB*NN*HH];  // [b][n][h]
__device__ float g_m[2][(size_t)BB*NN*HH];   // ping-pong [b][n][h]
__device__ int   g_deg[NN];
__device__ int   g_rowptr[NN+1];
__device__ int   g_csrc[EE];
__device__ float g_losspart[NN];
__device__ int   g_maskcnt;
__device__ int   g_masktype;                 // 0=uint8, 1=int32, 2=float32

__device__ __forceinline__ unsigned short f2bf(float f) {
    __nv_bfloat16 h = __float2bfloat16(f);
    return *reinterpret_cast<unsigned short*>(&h);
}
__device__ __forceinline__ int mask_at(const void* m, size_t i, int mt) {
    if (mt == 2) return ((const float*)m)[i] != 0.f;
    if (mt == 1) return ((const int*)m)[i]   != 0;
    return ((const unsigned char*)m)[i] != 0;
}

#define FMA2(d, a, b) asm("fma.rn.f32x2 %0, %1, %2, %3;" : "=l"(d) : "l"(a), "l"(b), "l"(d))
#define SPLAT2(d, w)  asm("mov.b64 %0, {%1, %1};" : "=l"(d) : "r"(w))
#define UNPK2(lo, hi, v) asm("mov.b64 {%0, %1}, %2;" : "=f"(lo), "=f"(hi) : "l"(v))

// ---------------- prologue A: weight transposes + detect + init ----------------
__global__ void kA(const float* __restrict__ Wih, const float* __restrict__ Whh,
                   const float* __restrict__ Wmix, const float* __restrict__ Wmsg,
                   const float* __restrict__ b_msg, const unsigned int* __restrict__ maskw) {
    int tid = threadIdx.x; // 256
    if (blockIdx.x < 4096) {
        // init slice (4096*256 == 1,048,576 == B*N*H exactly)
        int i = blockIdx.x*256 + tid;
        g_state[i] = 0.f;
        g_m[0][i]  = b_msg[i & 63];
        if (i < NN) g_losspart[i] = 0.f;
        if (i == 0) g_maskcnt = 0;
        // big-weight transpose [g][k] -> [k][g] bf16
        int n    = blockIdx.x >> 1;
        int koff = (blockIdx.x & 1) * 32;
        __shared__ float tile[192*33];
        for (int pass = 0; pass < 2; ++pass) {
            const float* W = pass ? Whh : Wih;
            unsigned short* O = pass ? g_Whh : g_Wih;
            for (int i2 = tid; i2 < 192*32; i2 += 256) {
                int g = i2 >> 5, kk = i2 & 31;
                tile[g*33 + kk] = W[((size_t)n*192 + g)*64 + koff + kk];
            }
            __syncthreads();
            for (int o = tid; o < 32*192; o += 256) {
                int kk = o / 192, g = o % 192;
                O[((size_t)n*64 + koff + kk)*192 + g] = f2bf(tile[g*33 + kk]);
            }
            __syncthreads();
        }
    } else {
        // small transposes
        for (int i = tid; i < 128*64; i += 256) {
            int k = i / 64, h = i % 64;
            g_Wmix_t[i] = Wmix[h*128 + k];
        }
        for (int i = tid; i < 64*64; i += 256) {
            int k = i / 64, h = i % 64;
            g_Wmsg_t[i] = Wmsg[h*64 + k];
        }
        // mask dtype autodetect (first 16KB)
        __shared__ int sI, sF;
        if (tid == 0) { sI = 1; sF = 1; }
        __syncthreads();
        int okI = 1, okF = 1;
        for (int i = tid; i < 4096; i += 256) {
            unsigned v = maskw[i];
            okI &= (v <= 1u) ? 1 : 0;
            okF &= (v == 0u || v == 0x3F800000u) ? 1 : 0;
        }
        if (!okI) atomicAnd(&sI, 0);
        if (!okF) atomicAnd(&sF, 0);
        __syncthreads();
        if (tid == 0) g_masktype = sF ? 2 : (sI ? 1 : 0);
    }
}

// ---------------- CSR build ----------------
__global__ void k_count(const int* __restrict__ ei) {
    const int* dst = ei + EE;
    int w    = (blockIdx.x*blockDim.x + threadIdx.x) >> 5;
    int lane = threadIdx.x & 31;
    if (w >= NN) return;
    int cnt = 0;
    for (int e = lane; e < EE; e += 32) cnt += (dst[e] == w) ? 1 : 0;
    #pragma unroll
    for (int off = 16; off; off >>= 1) cnt += __shfl_down_sync(0xffffffffu, cnt, off);
    if (lane == 0) g_deg[w] = cnt;
}

__global__ void k_scan() {
    __shared__ int s[NN];
    int t = threadIdx.x; // 1024
    s[t] = g_deg[t]; s[t+1024] = g_deg[t+1024];
    __syncthreads();
    for (int off = 1; off < NN; off <<= 1) {
        int v0 = s[t], v1 = s[t+1024];
        int u0 = (t >= off) ? s[t-off] : 0;
        int u1 = ((t+1024) >= off) ? s[t+1024-off] : 0;
        __syncthreads();
        s[t] = v0 + u0; s[t+1024] = v1 + u1;
        __syncthreads();
    }
    g_rowptr[t+1] = s[t];
    g_rowptr[t+1025] = s[t+1024];
    if (t == 0) g_rowptr[0] = 0;
}

__global__ void k_fillmask(const int* __restrict__ ei, const void* __restrict__ m) {
    const int* src = ei;
    const int* dst = ei + EE;
    int w    = (blockIdx.x*blockDim.x + threadIdx.x) >> 5;
    int lane = threadIdx.x & 31;
    if (w < NN) {
        int off = g_rowptr[w];
        for (int base = 0; base < EE; base += 32) {
            int e = base + lane;
            bool match = (dst[e] == w);
            unsigned bal = __ballot_sync(0xffffffffu, match);
            if (match) {
                int pos = off + __popc(bal & ((1u << lane) - 1u));
                g_csrc[pos] = src[e];
            }
            off += __popc(bal);
        }
    }
    // masked-count
    __shared__ int sh[256];
    int mt = g_masktype;
    int tid = threadIdx.x;
    int cnt = 0;
    for (size_t i = (size_t)blockIdx.x*256 + tid; i < (size_t)BB*TT*NN; i += (size_t)gridDim.x*256)
        cnt += mask_at(m, i, mt);
    sh[tid] = cnt; __syncthreads();
    for (int off = 128; off; off >>= 1) { if (tid < off) sh[tid] += sh[tid+off]; __syncthreads(); }
    if (tid == 0) atomicAdd(&g_maskcnt, sh[0]);
}

// ---------------- fused per-timestep kernel ----------------
// Thread plan (384 threads):
//  P0/P1 : [0,128) state load, [128,256) x load, [256,384) edge gather
//  P2    : [0,256) = (b, h4, ks2)      -> m2t (staged)
//  P3    : 384 = half(2) x kq(4) x g4(48), f32x2, staged reduction -> gi/gh
//  P4    : all, 512 items
//  P5    : [0,256) = (b, h4, ks2)      -> mnext (staged)   |  P6: [256,264) loss
__global__ __launch_bounds__(384, 2) void k_step(
    const float* __restrict__ x, const float* __restrict__ targets,
    const void* __restrict__ tmask,
    const float* __restrict__ b_msg, const float* __restrict__ b_mix,
    const float* __restrict__ b_ih, const float* __restrict__ b_hh,
    const float* __restrict__ W_read, const float* __restrict__ b_read,
    int t, int parity)
{
    const int n   = blockIdx.x;
    const int tid = threadIdx.x;
    const float* __restrict__ mprev = g_m[parity];
    float* __restrict__ mnext = g_m[parity ^ 1];

    __shared__ __align__(16) float st_s[512];    // [b][h]  (P4)
    __shared__ __align__(16) float x_s[512];     // [b][h]  (P2), scratch for P5
    __shared__ __align__(16) float agg_s[512];   // [b][h]  (P2)
    __shared__ __align__(8)  float stt[640];     // [h*10+b] (P3)
    __shared__ __align__(8)  float m2t[640];     // [h*10+b] (P3)
    __shared__ __align__(8)  float nst[640];     // [h*10+b] (P5,P6)
    __shared__ __align__(16) float gi_s[8*GG];   // [b][g]
    __shared__ __align__(16) float gh_s[8*GG];   // [b][g]

    // ================= P0 + P1 (disjoint thread groups) =================
    if (tid < 128) {
        int b = tid >> 4, h4 = tid & 15;
        float4 v = *(const float4*)&g_state[((size_t)b*NN + n)*HH + h4*4];
        *(float4*)&st_s[b*64 + h4*4] = v;
        stt[(h4*4+0)*10 + b] = v.x;
        stt[(h4*4+1)*10 + b] = v.y;
        stt[(h4*4+2)*10 + b] = v.z;
        stt[(h4*4+3)*10 + b] = v.w;
    } else if (tid < 256) {
        int q = tid - 128, b = q >> 4, h4 = q & 15;
        float4 v = *(const float4*)&x[(((size_t)b*TT + t)*NN + n)*FF + h4*4];
        *(float4*)&x_s[b*64 + h4*4] = v;
    } else {
        int q = tid - 256, b = q >> 4, h4 = q & 15;
        int rs = g_rowptr[n], re = g_rowptr[n+1];
        float4 a = make_float4(0.f, 0.f, 0.f, 0.f);
        #pragma unroll 2
        for (int e = rs; e < re; ++e) {
            int s = __ldg(&g_csrc[e]);
            float4 v = *(const float4*)&mprev[((size_t)b*NN + s)*HH + h4*4];
            a.x += v.x; a.y += v.y; a.z += v.z; a.w += v.w;
        }
        *(float4*)&agg_s[b*64 + h4*4] = a;
    }
    __syncthreads();

    // ================= P2: m2 = W_mix @ [agg|x] + b_mix  -> m2t =================
    float p2a0 = 0.f, p2a1 = 0.f, p2a2 = 0.f, p2a3 = 0.f;
    int p2b = 0, p2h4 = 0, p2ks = 0;
    if (tid < 256) {
        p2b  = tid >> 5;
        p2h4 = (tid >> 1) & 15;
        p2ks = tid & 1;
        const float* vec = p2ks ? &x_s[p2b*64] : &agg_s[p2b*64];
        const float* W   = &g_Wmix_t[(p2ks*64)*64 + p2h4*4];
        #pragma unroll 8
        for (int k = 0; k < 64; ++k) {
            float4 w = *(const float4*)&W[k*64];
            float s = vec[k];
            p2a0 = fmaf(w.x, s, p2a0);
            p2a1 = fmaf(w.y, s, p2a1);
            p2a2 = fmaf(w.z, s, p2a2);
            p2a3 = fmaf(w.w, s, p2a3);
        }
        if (p2ks == 0) {
            int h = p2h4*4;
            m2t[(h+0)*10 + p2b] = b_mix[h+0] + p2a0;
            m2t[(h+1)*10 + p2b] = b_mix[h+1] + p2a1;
            m2t[(h+2)*10 + p2b] = b_mix[h+2] + p2a2;
            m2t[(h+3)*10 + p2b] = b_mix[h+3] + p2a3;
        }
    }
    __syncthreads();
    if (tid < 256 && p2ks == 1) {
        int h = p2h4*4;
        m2t[(h+0)*10 + p2b] += p2a0;
        m2t[(h+1)*10 + p2b] += p2a1;
        m2t[(h+2)*10 + p2b] += p2a2;
        m2t[(h+3)*10 + p2b] += p2a3;
    }
    __syncthreads();

    // ================= P3: gi/gh via f32x2 packed FFMA =================
    unsigned long long acc[16];
    int p3half, p3kq, p3g4;
    {
        p3half = (tid >= 192) ? 1 : 0;
        int q  = p3half ? tid - 192 : tid;
        p3kq = q / 48;
        p3g4 = q - p3kq*48;
        const unsigned short* __restrict__ Wp =
            (p3half ? g_Whh : g_Wih) + ((size_t)n*64 + p3kq*16)*192 + p3g4*4;
        const float* __restrict__ vecT = p3half ? stt : m2t;
        int k10 = (p3kq*16)*10;
        #pragma unroll
        for (int i = 0; i < 16; ++i) acc[i] = 0ull;
        #pragma unroll 2
        for (int k = 0; k < 16; ++k) {
            uint2 wb = __ldcs((const uint2*)Wp);
            Wp += GG;
            unsigned w0b = wb.x << 16, w1b = wb.x & 0xFFFF0000u;
            unsigned w2b = wb.y << 16, w3b = wb.y & 0xFFFF0000u;
            unsigned long long W0, W1, W2, W3;
            SPLAT2(W0, w0b); SPLAT2(W1, w1b); SPLAT2(W2, w2b); SPLAT2(W3, w3b);
            unsigned long long v0 = *(const unsigned long long*)&vecT[k10 + 0];
            unsigned long long v1 = *(const unsigned long long*)&vecT[k10 + 2];
            unsigned long long v2 = *(const unsigned long long*)&vecT[k10 + 4];
            unsigned long long v3 = *(const unsigned long long*)&vecT[k10 + 6];
            k10 += 10;
            FMA2(acc[ 0], W0, v0); FMA2(acc[ 1], W0, v1); FMA2(acc[ 2], W0, v2); FMA2(acc[ 3], W0, v3);
            FMA2(acc[ 4], W1, v0); FMA2(acc[ 5], W1, v1); FMA2(acc[ 6], W1, v2); FMA2(acc[ 7], W1, v3);
            FMA2(acc[ 8], W2, v0); FMA2(acc[ 9], W2, v1); FMA2(acc[10], W2, v2); FMA2(acc[11], W2, v3);
            FMA2(acc[12], W3, v0); FMA2(acc[13], W3, v1); FMA2(acc[14], W3, v2); FMA2(acc[15], W3, v3);
        }
    }
    // staged deterministic reduction over kq, bias at stage 0
    {
        float* out = p3half ? gh_s : gi_s;
        const float* bias = p3half ? b_hh : b_ih;
        #pragma unroll 1
        for (int s = 0; s < 4; ++s) {
            if (p3kq == s) {
                int gg = p3g4*4;
                #pragma unroll
                for (int bp = 0; bp < 4; ++bp) {
                    float lo0, hi0, lo1, hi1, lo2, hi2, lo3, hi3;
                    UNPK2(lo0, hi0, acc[0*4 + bp]);
                    UNPK2(lo1, hi1, acc[1*4 + bp]);
                    UNPK2(lo2, hi2, acc[2*4 + bp]);
                    UNPK2(lo3, hi3, acc[3*4 + bp]);
                    float4 lo4 = make_float4(lo0, lo1, lo2, lo3);
                    float4 hi4 = make_float4(hi0, hi1, hi2, hi3);
                    if (s == 0) {
                        float4 bv = *(const float4*)&bias[(size_t)n*GG + gg];
                        lo4.x += bv.x; lo4.y += bv.y; lo4.z += bv.z; lo4.w += bv.w;
                        hi4.x += bv.x; hi4.y += bv.y; hi4.z += bv.z; hi4.w += bv.w;
                        *(float4*)&out[(2*bp  )*GG + gg] = lo4;
                        *(float4*)&out[(2*bp+1)*GG + gg] = hi4;
                    } else {
                        float4 c0 = *(float4*)&out[(2*bp  )*GG + gg];
                        float4 c1 = *(float4*)&out[(2*bp+1)*GG + gg];
                        c0.x += lo4.x; c0.y += lo4.y; c0.z += lo4.z; c0.w += lo4.w;
                        c1.x += hi4.x; c1.y += hi4.y; c1.z += hi4.z; c1.w += hi4.w;
                        *(float4*)&out[(2*bp  )*GG + gg] = c0;
                        *(float4*)&out[(2*bp+1)*GG + gg] = c1;
                    }
                }
            }
            __syncthreads();
        }
    }

    // ================= P4: GRU elementwise =================
    for (int p = tid; p < 512; p += 384) {
        int b = p >> 6, h = p & 63;
        float ir = gi_s[b*GG + h],       hr = gh_s[b*GG + h];
        float iz = gi_s[b*GG + 64 + h],  hz = gh_s[b*GG + 64 + h];
        float in_= gi_s[b*GG + 128 + h], hn = gh_s[b*GG + 128 + h];
        float r  = 1.f / (1.f + __expf(-(ir + hr)));
        float z  = 1.f / (1.f + __expf(-(iz + hz)));
        float nc = tanhf(in_ + r * hn);
        float ns = (1.f - z) * nc + z * st_s[p];
        nst[h*10 + b] = ns;
        g_state[((size_t)b*NN + n)*HH + h] = ns;
    }
    __syncthreads();

    // ================= P5: mnext = W_msg @ ns + b_msg   |   P6: loss =================
    float p5a0 = 0.f, p5a1 = 0.f, p5a2 = 0.f, p5a3 = 0.f;
    if (tid < 256) {
        int b  = tid >> 5;
        int h4 = (tid >> 1) & 15;
        int ks = tid & 1;
        const float* W = &g_Wmsg_t[(ks*32)*64 + h4*4];
        int kb = ks*32*10 + b;
        #pragma unroll 8
        for (int k = 0; k < 32; ++k) {
            float4 w = *(const float4*)&W[k*64];
            float s = nst[kb + k*10];
            p5a0 = fmaf(w.x, s, p5a0);
            p5a1 = fmaf(w.y, s, p5a1);
            p5a2 = fmaf(w.z, s, p5a2);
            p5a3 = fmaf(w.w, s, p5a3);
        }
        if (ks == 0) {
            int h = h4*4;
            x_s[b*64 + h + 0] = b_msg[h+0] + p5a0;
            x_s[b*64 + h + 1] = b_msg[h+1] + p5a1;
            x_s[b*64 + h + 2] = b_msg[h+2] + p5a2;
            x_s[b*64 + h + 3] = b_msg[h+3] + p5a3;
        }
    } else if (tid < 264) {
        int b = tid - 256;
        float dot = b_read[0];
        #pragma unroll 8
        for (int h = 0; h < 64; ++h) dot = fmaf(W_read[h], nst[h*10 + b], dot);
        size_t ti = ((size_t)b*TT + t)*NN + n;
        float tv = targets[ti];
        float d  = dot - tv;
        int   mk = mask_at(tmask, ti, g_masktype);
        float l  = mk ? 0.5f * d * d : 0.f;
        #pragma unroll
        for (int off = 4; off; off >>= 1) l += __shfl_down_sync(0xFFu, l, off);
        if (b == 0) g_losspart[n] += l;
    }
    __syncthreads();
    if (tid < 256 && (tid & 1)) {
        int b  = tid >> 5;
        int h4 = (tid >> 1) & 15;
        int h  = h4*4;
        float4 o;
        o.x = x_s[b*64 + h + 0] + p5a0;
        o.y = x_s[b*64 + h + 1] + p5a1;
        o.z = x_s[b*64 + h + 2] + p5a2;
        o.w = x_s[b*64 + h + 3] + p5a3;
        *(float4*)&mnext[((size_t)b*NN + n)*HH + h] = o;
    }
}

// ---------------- finalize ----------------
__global__ void k_final(float* __restrict__ out) {
    __shared__ float sh[256];
    int tid = threadIdx.x;
    float s = 0.f;
    for (int i = tid; i < NN; i += 256) s += g_losspart[i];
    sh[tid] = s; __syncthreads();
    for (int off = 128; off; off >>= 1) { if (tid < off) sh[tid] += sh[tid+off]; __syncthreads(); }
    if (tid == 0) out[0] = sh[0] / (float)g_maskcnt;
}

// ---------------- launch ----------------
extern "C" void kernel_launch(void* const* d_in, const int* in_sizes, int n_in,
                              void* d_out, int out_size) {
    const float* x       = (const float*)d_in[0];
    const float* targets = (const float*)d_in[1];
    const void*  tmask   = (const void*)d_in[2];
    const int*   ei      = (const int*)d_in[3];
    const float* W_msg   = (const float*)d_in[4];
    const float* b_msg   = (const float*)d_in[5];
    const float* W_mix   = (const float*)d_in[6];
    const float* b_mix   = (const float*)d_in[7];
    const float* W_ih    = (const float*)d_in[8];
    const float* W_hh    = (const float*)d_in[9];
    const float* b_ih    = (const float*)d_in[10];
    const float* b_hh    = (const float*)d_in[11];
    const float* W_read  = (const float*)d_in[12];
    const float* b_read  = (const float*)d_in[13];

    kA<<<4097, 256>>>(W_ih, W_hh, W_mix, W_msg, b_msg, (const unsigned int*)tmask);
    k_count<<<256, 256>>>(ei);
    k_scan<<<1, 1024>>>();
    k_fillmask<<<256, 256>>>(ei, tmask);

    for (int t = 0; t < TT; ++t) {
        k_step<<<NN, 384>>>(x, targets, tmask, b_msg, b_mix, b_ih, b_hh,
                            W_read, b_read, t, t & 1);
    }
    k_final<<<1, 256>>>((float*)d_out);
}

// round 5
// speedup vs baseline: 1.2984x; 1.2528x over previous
#include <cuda_runtime.h>
#include <cuda_bf16.h>

#define BB 8
#define TT 64
#define NN 2048
#define GG 192
#define EE 32768
#define NBLK 256
#define NPB 8

#define WSZ (2048ULL*64*192)

// ---------------- device scratch ----------------
__device__ unsigned short g_Wih[WSZ];        // bf16 bits, [n][k][g]
__device__ unsigned short g_Whh[WSZ];        // bf16 bits, [n][k][g]
__device__ float g_Wmix_t[128*64];           // [k][h]
__device__ float g_Wmsg_t[64*64];            // [k][h]
__device__ float g_m[2][(size_t)BB*NN*64];   // message ping-pong [b][n][h]
__device__ int   g_deg[NN];
__device__ int   g_rowptr[NN+1];
__device__ int   g_csrc[EE];
__device__ float g_losspart[NN];
__device__ int   g_maskcnt;
__device__ int   g_masktype;                 // 0=uint8, 1=int32, 2=float32
__device__ unsigned g_cnt0[16];
__device__ unsigned g_cnt1;
__device__ unsigned g_gen;

__device__ __forceinline__ unsigned short f2bf(float f) {
    __nv_bfloat16 h = __float2bfloat16(f);
    return *reinterpret_cast<unsigned short*>(&h);
}
__device__ __forceinline__ int mask_at(const void* m, size_t i, int mt) {
    if (mt == 2) return ((const float*)m)[i] != 0.f;
    if (mt == 1) return ((const int*)m)[i]   != 0;
    return ((const unsigned char*)m)[i] != 0;
}

#define FMA2(d, a, b) asm("fma.rn.f32x2 %0, %1, %2, %3;" : "=l"(d) : "l"(a), "l"(b), "l"(d))
#define SPLAT2(d, w)  asm("mov.b64 %0, {%1, %1};" : "=l"(d) : "r"(w))
#define SPLATF(d, f)  asm("mov.b64 %0, {%1, %1};" : "=l"(d) : "f"(f))
#define UNPK2(lo, hi, v) asm("mov.b64 {%0, %1}, %2;" : "=f"(lo), "=f"(hi) : "l"(v))

__device__ __forceinline__ unsigned ld_vol(unsigned* p) {
    unsigned v; asm volatile("ld.volatile.global.u32 %0, [%1];" : "=r"(v) : "l"(p)); return v;
}

// ---------------- grid barrier (two-level, generation-based) ----------------
__device__ __forceinline__ void grid_barrier(int bid, int tid, unsigned t) {
    __syncthreads();
    if (tid == 0) {
        __threadfence();
        unsigned r = atomicAdd(&g_cnt0[bid >> 4], 1u);
        if (r == 15u) {
            unsigned r2 = atomicAdd(&g_cnt1, 1u);
            if (r2 == 15u) {
                g_cnt1 = 0u;
                #pragma unroll
                for (int i = 0; i < 16; ++i) g_cnt0[i] = 0u;
                __threadfence();
                atomicExch(&g_gen, t + 1u);
            }
        }
        while (ld_vol(&g_gen) <= t) __nanosleep(64);
        __threadfence();
    }
    __syncthreads();
}

// ---------------- prologue: transposes + init + detect + degree count ----------------
__global__ void kA(const float* __restrict__ Wih, const float* __restrict__ Whh,
                   const float* __restrict__ Wmix, const float* __restrict__ Wmsg,
                   const float* __restrict__ b_msg, const unsigned int* __restrict__ maskw,
                   const int* __restrict__ ei) {
    int tid = threadIdx.x; // 256
    if (blockIdx.x < 4096) {
        int i = blockIdx.x*256 + tid;
        g_m[0][i] = b_msg[i & 63];
        int n    = blockIdx.x >> 1;
        int koff = (blockIdx.x & 1) * 32;
        __shared__ float tile[192*33];
        for (int pass = 0; pass < 2; ++pass) {
            const float* W = pass ? Whh : Wih;
            unsigned short* O = pass ? g_Whh : g_Wih;
            for (int i2 = tid; i2 < 192*32; i2 += 256) {
                int g = i2 >> 5, kk = i2 & 31;
                tile[g*33 + kk] = W[((size_t)n*192 + g)*64 + koff + kk];
            }
            __syncthreads();
            for (int o = tid; o < 32*192; o += 256) {
                int kk = o / 192, g = o % 192;
                O[((size_t)n*64 + koff + kk)*192 + g] = f2bf(tile[g*33 + kk]);
            }
            __syncthreads();
        }
        // degree count for node = blockIdx.x (first 2048 blocks)
        if (blockIdx.x < NN) {
            const int* dst = ei + EE;
            int cnt = 0;
            for (int e = tid; e < EE; e += 256) cnt += (dst[e] == (int)blockIdx.x) ? 1 : 0;
            int* rc = (int*)tile;
            rc[tid] = cnt; __syncthreads();
            for (int off = 128; off; off >>= 1) { if (tid < off) rc[tid] += rc[tid+off]; __syncthreads(); }
            if (tid == 0) g_deg[blockIdx.x] = rc[0];
        }
    } else {
        for (int i = tid; i < 128*64; i += 256) {
            int k = i / 64, h = i % 64;
            g_Wmix_t[i] = Wmix[h*128 + k];
        }
        for (int i = tid; i < 64*64; i += 256) {
            int k = i / 64, h = i % 64;
            g_Wmsg_t[i] = Wmsg[h*64 + k];
        }
        __shared__ int sI, sF;
        if (tid == 0) { sI = 1; sF = 1; }
        __syncthreads();
        int okI = 1, okF = 1;
        for (int i = tid; i < 4096; i += 256) {
            unsigned v = maskw[i];
            okI &= (v <= 1u) ? 1 : 0;
            okF &= (v == 0u || v == 0x3F800000u) ? 1 : 0;
        }
        if (!okI) atomicAnd(&sI, 0);
        if (!okF) atomicAnd(&sF, 0);
        __syncthreads();
        if (tid == 0) {
            g_masktype = sF ? 2 : (sI ? 1 : 0);
            g_maskcnt = 0;
            g_cnt1 = 0u; g_gen = 0u;
            for (int i = 0; i < 16; ++i) g_cnt0[i] = 0u;
        }
    }
}

__global__ void k_scan() {
    __shared__ int s[NN];
    int t = threadIdx.x; // 1024
    s[t] = g_deg[t]; s[t+1024] = g_deg[t+1024];
    __syncthreads();
    for (int off = 1; off < NN; off <<= 1) {
        int v0 = s[t], v1 = s[t+1024];
        int u0 = (t >= off) ? s[t-off] : 0;
        int u1 = ((t+1024) >= off) ? s[t+1024-off] : 0;
        __syncthreads();
        s[t] = v0 + u0; s[t+1024] = v1 + u1;
        __syncthreads();
    }
    g_rowptr[t+1] = s[t];
    g_rowptr[t+1025] = s[t+1024];
    if (t == 0) g_rowptr[0] = 0;
}

__global__ void k_fillmask(const int* __restrict__ ei, const void* __restrict__ m) {
    const int* src = ei;
    const int* dst = ei + EE;
    int w    = (blockIdx.x*blockDim.x + threadIdx.x) >> 5;
    int lane = threadIdx.x & 31;
    if (w < NN) {
        int off = g_rowptr[w];
        for (int base = 0; base < EE; base += 32) {
            int e = base + lane;
            bool match = (dst[e] == w);
            unsigned bal = __ballot_sync(0xffffffffu, match);
            if (match) {
                int pos = off + __popc(bal & ((1u << lane) - 1u));
                g_csrc[pos] = src[e];
            }
            off += __popc(bal);
        }
    }
    __shared__ int sh[256];
    int mt = g_masktype;
    int tid = threadIdx.x;
    int cnt = 0;
    for (size_t i = (size_t)blockIdx.x*256 + tid; i < (size_t)BB*TT*NN; i += (size_t)gridDim.x*256)
        cnt += mask_at(m, i, mt);
    sh[tid] = cnt; __syncthreads();
    for (int off = 128; off; off >>= 1) { if (tid < off) sh[tid] += sh[tid+off]; __syncthreads(); }
    if (tid == 0) atomicAdd(&g_maskcnt, sh[0]);
}

// ---------------- persistent all-timesteps kernel ----------------
// smem layout (floats):
//  sWmix 8192 | sWmsg 4096 | sSt 8*640 | xt 640 | agt 640 | m2t 640
//  | gi 1536 | gh 1536 | scr 8*512 | sLoss 8
#define SMEM_FLOATS (8192 + 4096 + 5120 + 640 + 640 + 640 + 1536 + 1536 + 4096 + 8)
#define SMEM_BYTES  (SMEM_FLOATS * 4)

__global__ __launch_bounds__(384, 2) void k_persist(
    const float* __restrict__ x, const float* __restrict__ targets,
    const void* __restrict__ tmask,
    const float* __restrict__ b_msg, const float* __restrict__ b_mix,
    const float* __restrict__ b_ih, const float* __restrict__ b_hh,
    const float* __restrict__ W_read, const float* __restrict__ b_read)
{
    extern __shared__ float sm[];
    float* sWmix = sm;                  // [k(128)][h(64)]
    float* sWmsg = sWmix + 8192;        // [k(64)][h(64)]
    float* sSt   = sWmsg + 4096;        // [node(8)][h*10+b]
    float* xt    = sSt   + 5120;        // [k*10+b]
    float* agt   = xt    + 640;         // [k*10+b]
    float* m2t   = agt   + 640;         // [k*10+b]
    float* gi    = m2t   + 640;         // [b][g(192)]
    float* gh    = gi    + 1536;
    float* scr   = gh    + 1536;        // [ks(8)][b*64+h]
    float* sLoss = scr   + 4096;        // [8]

    const int tid = threadIdx.x;
    const int bid = blockIdx.x;
    const int n0  = bid * NPB;
    const int mt  = g_masktype;

    for (int i = tid; i < 8192/4; i += 384) ((float4*)sWmix)[i] = ((const float4*)g_Wmix_t)[i];
    for (int i = tid; i < 4096/4; i += 384) ((float4*)sWmsg)[i] = ((const float4*)g_Wmsg_t)[i];
    for (int i = tid; i < 5120; i += 384) sSt[i] = 0.f;
    if (tid < 8) sLoss[tid] = 0.f;
    __syncthreads();

    for (int t = 0; t < TT; ++t) {
        const float* __restrict__ mprev = g_m[t & 1];
        float* __restrict__ mnext = g_m[(t + 1) & 1];

        for (int ni = 0; ni < NPB; ++ni) {
            const int n = n0 + ni;
            float* stn = sSt + ni * 640;

            // ---- P0 (x load) + P1 (edge gather), disjoint thread groups ----
            float4 ga = make_float4(0.f,0.f,0.f,0.f);
            int ges = -1, gb = 0, gh4 = 0;
            if (tid < 128) {
                int b = tid >> 4, h4 = tid & 15;
                float4 v = *(const float4*)&x[(((size_t)b*TT + t)*NN + n)*64 + h4*4];
                xt[(h4*4+0)*10+b] = v.x; xt[(h4*4+1)*10+b] = v.y;
                xt[(h4*4+2)*10+b] = v.z; xt[(h4*4+3)*10+b] = v.w;
            } else {
                int q = tid - 128;
                gb = q >> 5; gh4 = (q >> 1) & 15; ges = q & 1;
                int rs = g_rowptr[n], re = g_rowptr[n+1];
                #pragma unroll 2
                for (int e = rs + ges; e < re; e += 2) {
                    int s = __ldg(&g_csrc[e]);
                    float4 v = *(const float4*)&mprev[((size_t)gb*NN + s)*64 + gh4*4];
                    ga.x += v.x; ga.y += v.y; ga.z += v.z; ga.w += v.w;
                }
                if (ges == 0) {
                    agt[(gh4*4+0)*10+gb] = ga.x; agt[(gh4*4+1)*10+gb] = ga.y;
                    agt[(gh4*4+2)*10+gb] = ga.z; agt[(gh4*4+3)*10+gb] = ga.w;
                }
            }
            __syncthreads();
            if (ges == 1) {
                agt[(gh4*4+0)*10+gb] += ga.x; agt[(gh4*4+1)*10+gb] += ga.y;
                agt[(gh4*4+2)*10+gb] += ga.z; agt[(gh4*4+3)*10+gb] += ga.w;
            }
            __syncthreads();

            // ---- P2: m2 = W_mix @ [agg|x] + b_mix, f32x2, ks8 partials ----
            if (tid < 256) {
                int hp = tid & 31, ks = tid >> 5;   // h pair, k chunk of 16
                int k0 = ks * 16;
                const float* vt = (ks < 4) ? agt : xt;
                int kb = (ks < 4 ? k0 : k0 - 64) * 10;
                unsigned long long acc[8];
                #pragma unroll
                for (int i = 0; i < 8; ++i) acc[i] = 0ull;
                const float* Wr = &sWmix[k0*64 + hp*2];
                #pragma unroll 4
                for (int kk = 0; kk < 16; ++kk) {
                    unsigned long long W2 = *(const unsigned long long*)Wr;
                    Wr += 64;
                    float wl, wh; UNPK2(wl, wh, W2);
                    unsigned long long W0, W1; SPLATF(W0, wl); SPLATF(W1, wh);
                    unsigned long long v0 = *(const unsigned long long*)&vt[kb + 0];
                    unsigned long long v1 = *(const unsigned long long*)&vt[kb + 2];
                    unsigned long long v2 = *(const unsigned long long*)&vt[kb + 4];
                    unsigned long long v3 = *(const unsigned long long*)&vt[kb + 6];
                    kb += 10;
                    FMA2(acc[0], W0, v0); FMA2(acc[1], W0, v1); FMA2(acc[2], W0, v2); FMA2(acc[3], W0, v3);
                    FMA2(acc[4], W1, v0); FMA2(acc[5], W1, v1); FMA2(acc[6], W1, v2); FMA2(acc[7], W1, v3);
                }
                int h0 = hp*2;
                #pragma unroll
                for (int bp = 0; bp < 4; ++bp) {
                    float lo, hi;
                    UNPK2(lo, hi, acc[bp]);
                    scr[ks*512 + (2*bp  )*64 + h0] = lo;
                    scr[ks*512 + (2*bp+1)*64 + h0] = hi;
                    UNPK2(lo, hi, acc[4+bp]);
                    scr[ks*512 + (2*bp  )*64 + h0+1] = lo;
                    scr[ks*512 + (2*bp+1)*64 + h0+1] = hi;
                }
            }
            __syncthreads();
            if (tid < 128) {
                int b = tid >> 4, h4 = tid & 15;
                #pragma unroll
                for (int j = 0; j < 4; ++j) {
                    int h = h4*4 + j;
                    float s = b_mix[h];
                    #pragma unroll
                    for (int ks = 0; ks < 8; ++ks) s += scr[ks*512 + b*64 + h];
                    m2t[h*10 + b] = s;
                }
            }
            __syncthreads();

            // ---- P3: gi/gh (bf16 weight stream, f32x2), kq2 staged ----
            {
                int half = (tid >= 192) ? 1 : 0;
                int q  = half ? tid - 192 : tid;
                int kq = q / 96;
                int g2 = q - kq*96;
                const unsigned short* __restrict__ Wp =
                    (half ? g_Whh : g_Wih) + ((size_t)n*64 + kq*32)*192 + g2*2;
                const float* __restrict__ vecT = half ? stn : m2t;
                int kb = kq*32*10;
                unsigned long long acc[8];
                #pragma unroll
                for (int i = 0; i < 8; ++i) acc[i] = 0ull;
                #pragma unroll 4
                for (int kk = 0; kk < 32; ++kk) {
                    unsigned wb = *(const unsigned*)Wp;
                    Wp += GG;
                    unsigned w0b = wb << 16, w1b = wb & 0xFFFF0000u;
                    unsigned long long W0, W1; SPLAT2(W0, w0b); SPLAT2(W1, w1b);
                    unsigned long long v0 = *(const unsigned long long*)&vecT[kb + 0];
                    unsigned long long v1 = *(const unsigned long long*)&vecT[kb + 2];
                    unsigned long long v2 = *(const unsigned long long*)&vecT[kb + 4];
                    unsigned long long v3 = *(const unsigned long long*)&vecT[kb + 6];
                    kb += 10;
                    FMA2(acc[0], W0, v0); FMA2(acc[1], W0, v1); FMA2(acc[2], W0, v2); FMA2(acc[3], W0, v3);
                    FMA2(acc[4], W1, v0); FMA2(acc[5], W1, v1); FMA2(acc[6], W1, v2); FMA2(acc[7], W1, v3);
                }
                float* out = half ? gh : gi;
                const float* bias = half ? b_hh : b_ih;
                int gg = g2*2;
                #pragma unroll 1
                for (int s = 0; s < 2; ++s) {
                    if (kq == s) {
                        if (s == 0) {
                            float bv0 = bias[(size_t)n*GG + gg];
                            float bv1 = bias[(size_t)n*GG + gg + 1];
                            #pragma unroll
                            for (int bp = 0; bp < 4; ++bp) {
                                float lo, hi;
                                UNPK2(lo, hi, acc[bp]);
                                out[(2*bp  )*GG + gg] = bv0 + lo;
                                out[(2*bp+1)*GG + gg] = bv0 + hi;
                                UNPK2(lo, hi, acc[4+bp]);
                                out[(2*bp  )*GG + gg+1] = bv1 + lo;
                                out[(2*bp+1)*GG + gg+1] = bv1 + hi;
                            }
                        } else {
                            #pragma unroll
                            for (int bp = 0; bp < 4; ++bp) {
                                float lo, hi;
                                UNPK2(lo, hi, acc[bp]);
                                out[(2*bp  )*GG + gg] += lo;
                                out[(2*bp+1)*GG + gg] += hi;
                                UNPK2(lo, hi, acc[4+bp]);
                                out[(2*bp  )*GG + gg+1] += lo;
                                out[(2*bp+1)*GG + gg+1] += hi;
                            }
                        }
                    }
                    __syncthreads();
                }
            }

            // ---- P4: GRU elementwise, state updated in smem ----
            for (int p = tid; p < 512; p += 384) {
                int b = p >> 6, h = p & 63;
                float ir = gi[b*GG + h],       hr = gh[b*GG + h];
                float iz = gi[b*GG + 64 + h],  hz = gh[b*GG + 64 + h];
                float in_= gi[b*GG + 128 + h], hn = gh[b*GG + 128 + h];
                float r  = 1.f / (1.f + __expf(-(ir + hr)));
                float z  = 1.f / (1.f + __expf(-(iz + hz)));
                float nc = tanhf(in_ + r * hn);
                float old = stn[h*10 + b];
                stn[h*10 + b] = (1.f - z) * nc + z * old;
            }
            __syncthreads();

            // ---- P5: mnext = W_msg @ ns + b_msg (f32x2, ks8) | P6: loss ----
            if (tid < 256) {
                int hp = tid & 31, ks = tid >> 5;   // k chunk of 8
                int k0 = ks * 8;
                int kb = k0 * 10;
                unsigned long long acc[8];
                #pragma unroll
                for (int i = 0; i < 8; ++i) acc[i] = 0ull;
                const float* Wr = &sWmsg[k0*64 + hp*2];
                #pragma unroll
                for (int kk = 0; kk < 8; ++kk) {
                    unsigned long long W2 = *(const unsigned long long*)Wr;
                    Wr += 64;
                    float wl, wh; UNPK2(wl, wh, W2);
                    unsigned long long W0, W1; SPLATF(W0, wl); SPLATF(W1, wh);
                    unsigned long long v0 = *(const unsigned long long*)&stn[kb + 0];
                    unsigned long long v1 = *(const unsigned long long*)&stn[kb + 2];
                    unsigned long long v2 = *(const unsigned long long*)&stn[kb + 4];
                    unsigned long long v3 = *(const unsigned long long*)&stn[kb + 6];
                    kb += 10;
                    FMA2(acc[0], W0, v0); FMA2(acc[1], W0, v1); FMA2(acc[2], W0, v2); FMA2(acc[3], W0, v3);
                    FMA2(acc[4], W1, v0); FMA2(acc[5], W1, v1); FMA2(acc[6], W1, v2); FMA2(acc[7], W1, v3);
                }
                int h0 = hp*2;
                #pragma unroll
                for (int bp = 0; bp < 4; ++bp) {
                    float lo, hi;
                    UNPK2(lo, hi, acc[bp]);
                    scr[ks*512 + (2*bp  )*64 + h0] = lo;
                    scr[ks*512 + (2*bp+1)*64 + h0] = hi;
                    UNPK2(lo, hi, acc[4+bp]);
                    scr[ks*512 + (2*bp  )*64 + h0+1] = lo;
                    scr[ks*512 + (2*bp+1)*64 + h0+1] = hi;
                }
            } else if (tid < 264) {
                int b = tid - 256;
                float dot = b_read[0];
                #pragma unroll 8
                for (int h = 0; h < 64; ++h) dot = fmaf(W_read[h], stn[h*10 + b], dot);
                size_t ti = ((size_t)b*TT + t)*NN + n;
                float tv = targets[ti];
                float d  = dot - tv;
                int   mk = mask_at(tmask, ti, mt);
                float l  = mk ? 0.5f * d * d : 0.f;
                #pragma unroll
                for (int off = 4; off; off >>= 1) l += __shfl_down_sync(0xFFu, l, off);
                if (b == 0) sLoss[ni] += l;
            }
            __syncthreads();
            if (tid < 128) {
                int b = tid >> 4, h4 = tid & 15;
                float4 o;
                float* op = (float*)&o;
                #pragma unroll
                for (int j = 0; j < 4; ++j) {
                    int h = h4*4 + j;
                    float s = b_msg[h];
                    #pragma unroll
                    for (int ks = 0; ks < 8; ++ks) s += scr[ks*512 + b*64 + h];
                    op[j] = s;
                }
                *(float4*)&mnext[((size_t)b*NN + n)*64 + h4*4] = o;
            }
            __syncthreads();
        }

        if (t < TT - 1) grid_barrier(bid, tid, (unsigned)t);
    }

    __syncthreads();
    if (tid < 8) g_losspart[n0 + tid] = sLoss[tid];
}

// ---------------- finalize ----------------
__global__ void k_final(float* __restrict__ out) {
    __shared__ float sh[256];
    int tid = threadIdx.x;
    float s = 0.f;
    for (int i = tid; i < NN; i += 256) s += g_losspart[i];
    sh[tid] = s; __syncthreads();
    for (int off = 128; off; off >>= 1) { if (tid < off) sh[tid] += sh[tid+off]; __syncthreads(); }
    if (tid == 0) out[0] = sh[0] / (float)g_maskcnt;
}

// ---------------- launch ----------------
extern "C" void kernel_launch(void* const* d_in, const int* in_sizes, int n_in,
                              void* d_out, int out_size) {
    const float* x       = (const float*)d_in[0];
    const float* targets = (const float*)d_in[1];
    const void*  tmask   = (const void*)d_in[2];
    const int*   ei      = (const int*)d_in[3];
    const float* W_msg   = (const float*)d_in[4];
    const float* b_msg   = (const float*)d_in[5];
    const float* W_mix   = (const float*)d_in[6];
    const float* b_mix   = (const float*)d_in[7];
    const float* W_ih    = (const float*)d_in[8];
    const float* W_hh    = (const float*)d_in[9];
    const float* b_ih    = (const float*)d_in[10];
    const float* b_hh    = (const float*)d_in[11];
    const float* W_read  = (const float*)d_in[12];
    const float* b_read  = (const float*)d_in[13];

    cudaFuncSetAttribute(k_persist, cudaFuncAttributeMaxDynamicSharedMemorySize, SMEM_BYTES);

    kA<<<4097, 256>>>(W_ih, W_hh, W_mix, W_msg, b_msg, (const unsigned int*)tmask, ei);
    k_scan<<<1, 1024>>>();
    k_fillmask<<<256, 256>>>(ei, tmask);
    k_persist<<<NBLK, 384, SMEM_BYTES>>>(x, targets, tmask, b_msg, b_mix,
                                         b_ih, b_hh, W_read, b_read);
    k_final<<<1, 256>>>((float*)d_out);
}